// round 5
// baseline (speedup 1.0000x reference)
#include <cuda_runtime.h>

// ---------------------------------------------------------------------------
// Problem constants
// ---------------------------------------------------------------------------
#define N_PFAS 50000
#define N_GW   200000
#define N_SW   20000
#define D      32
#define E_PG   2000000
#define E_GP   2000000
#define E_PS   1000000
#define E_SP   1000000

#define OFF_Y   (N_PFAS * D)
#define OFF_SW  (N_PFAS * D + N_GW)

// Concatenated node space: [gw(pg) | pfas(gp) | pfas(sp) | sw(ps)]
#define NBASE1  N_GW
#define NBASE2  (N_GW + N_PFAS)
#define NBASE3  (N_GW + 2 * N_PFAS)
#define NTOT    (N_GW + 2 * N_PFAS + N_SW)     // 320000

// Concatenated edge space: [pg | gp | sp | ps]
#define EBASE1  E_PG
#define EBASE2  (E_PG + E_GP)
#define EBASE3  (E_PG + E_GP + E_SP)
#define ETOT    (E_PG + E_GP + E_SP + E_SP)    // 6,000,000

#define NB_SCAN ((NTOT + 1023) / 1024)         // 313

#define NB_GW  ((N_GW + 255) / 256)
#define NB_PF  ((N_PFAS + 255) / 256)
#define NB_SW  ((N_SW + 255) / 256)

typedef unsigned long long u64;

// ---------------------------------------------------------------------------
// Scratch (device globals; allocation-free)
// ---------------------------------------------------------------------------
__device__ int g_cnt_all[NTOT];
__device__ int g_cur_all[NTOT];
__device__ int g_off_all[NTOT];      // block-local exclusive scan
__device__ int g_bsum[NB_SCAN + 7];
__device__ int g_boff[NB_SCAN + 7];  // exclusive scan of block sums
__device__ int g_maxe_pg[N_GW];
__device__ int g_maxe_gp[N_PFAS];
__device__ int g_srcid[ETOT];
__device__ __align__(16) float g_sum_all[(size_t)NTOT * D];

// ---------------------------------------------------------------------------
// Packed f32x2 helpers (sm_100+)
// ---------------------------------------------------------------------------
__device__ __forceinline__ u64 pk2(float x) {
    u64 d; unsigned xi = __float_as_uint(x);
    asm("mov.b64 %0, {%1, %1};" : "=l"(d) : "r"(xi));
    return d;
}
__device__ __forceinline__ u64 pk2f(float a, float b) {
    u64 d; unsigned ai = __float_as_uint(a), bi = __float_as_uint(b);
    asm("mov.b64 %0, {%1, %2};" : "=l"(d) : "r"(ai), "r"(bi));
    return d;
}
__device__ __forceinline__ u64 f2fma(u64 a, u64 b, u64 c) {
    u64 d; asm("fma.rn.f32x2 %0, %1, %2, %3;" : "=l"(d) : "l"(a), "l"(b), "l"(c));
    return d;
}
__device__ __forceinline__ u64 f2add(u64 a, u64 b) {
    u64 d; asm("add.rn.f32x2 %0, %1, %2;" : "=l"(d) : "l"(a), "l"(b));
    return d;
}
__device__ __forceinline__ float2 up2(u64 a) {
    unsigned lo, hi;
    asm("mov.b64 {%0, %1}, %2;" : "=r"(lo), "=r"(hi) : "l"(a));
    return make_float2(__uint_as_float(lo), __uint_as_float(hi));
}

// ---------------------------------------------------------------------------
// 1) init: zero counts/cursors, maxe = -1
// ---------------------------------------------------------------------------
__global__ void k_init() {
    int i = blockIdx.x * blockDim.x + threadIdx.x;
    int stride = gridDim.x * blockDim.x;
    for (int j = i; j < NTOT; j += stride) { g_cnt_all[j] = 0; g_cur_all[j] = 0; }
    for (int j = i; j < N_GW; j += stride) g_maxe_pg[j] = -1;
    for (int j = i; j < N_PFAS; j += stride) g_maxe_gp[j] = -1;
}

// ---------------------------------------------------------------------------
// 2) count: 4 edges/thread, int atomics; also maxe for pg/gp
// ---------------------------------------------------------------------------
__global__ void k_count(const int* __restrict__ dst_pg, const int* __restrict__ dst_gp,
                        const int* __restrict__ dst_sp, const int* __restrict__ dst_ps)
{
    int q = blockIdx.x * blockDim.x + threadIdx.x;
    int e = q * 4;
    if (e >= ETOT) return;
    const int4* D4;
    int nb, rel, el;
    if (e < EBASE1)      { el = e;          D4 = (const int4*)dst_pg; nb = 0;      rel = 0; }
    else if (e < EBASE2) { el = e - EBASE1; D4 = (const int4*)dst_gp; nb = NBASE1; rel = 1; }
    else if (e < EBASE3) { el = e - EBASE2; D4 = (const int4*)dst_sp; nb = NBASE2; rel = 2; }
    else                 { el = e - EBASE3; D4 = (const int4*)dst_ps; nb = NBASE3; rel = 3; }
    int4 d = __ldg(&D4[el >> 2]);
    atomicAdd(&g_cnt_all[nb + d.x], 1);
    atomicAdd(&g_cnt_all[nb + d.y], 1);
    atomicAdd(&g_cnt_all[nb + d.z], 1);
    atomicAdd(&g_cnt_all[nb + d.w], 1);
    if (rel == 0) {
        atomicMax(&g_maxe_pg[d.x], el);
        atomicMax(&g_maxe_pg[d.y], el + 1);
        atomicMax(&g_maxe_pg[d.z], el + 2);
        atomicMax(&g_maxe_pg[d.w], el + 3);
    } else if (rel == 1) {
        atomicMax(&g_maxe_gp[d.x], el);
        atomicMax(&g_maxe_gp[d.y], el + 1);
        atomicMax(&g_maxe_gp[d.z], el + 2);
        atomicMax(&g_maxe_gp[d.w], el + 3);
    }
}

// ---------------------------------------------------------------------------
// 3) scan stage 1: per-1024-element block exclusive scan + block totals
// ---------------------------------------------------------------------------
__global__ void k_scan1() {
    __shared__ int sh[256];
    int tid = threadIdx.x;
    int base = blockIdx.x * 1024 + tid * 4;
    int4 c = make_int4(0, 0, 0, 0);
    if (base < NTOT) c = *(const int4*)&g_cnt_all[base];
    int tsum = c.x + c.y + c.z + c.w;
    sh[tid] = tsum;
    __syncthreads();
#pragma unroll
    for (int o = 1; o < 256; o <<= 1) {
        int v = (tid >= o) ? sh[tid - o] : 0;
        __syncthreads();
        sh[tid] += v;
        __syncthreads();
    }
    int excl = sh[tid] - tsum;
    if (tid == 255) g_bsum[blockIdx.x] = sh[255];
    if (base < NTOT) {
        int4 o4;
        o4.x = excl;
        o4.y = o4.x + c.x;
        o4.z = o4.y + c.y;
        o4.w = o4.z + c.z;
        *(int4*)&g_off_all[base] = o4;
    }
}

// scan stage 2: exclusive scan of the 313 block sums (single block)
__global__ void k_scan2() {
    __shared__ int sh[512];
    int tid = threadIdx.x;
    int v = (tid < NB_SCAN) ? g_bsum[tid] : 0;
    sh[tid] = v;
    __syncthreads();
#pragma unroll
    for (int o = 1; o < 512; o <<= 1) {
        int w = (tid >= o) ? sh[tid - o] : 0;
        __syncthreads();
        sh[tid] += w;
        __syncthreads();
    }
    if (tid < NB_SCAN) g_boff[tid] = sh[tid] - v;
}

// ---------------------------------------------------------------------------
// 4) fill: scatter src ids into CSR segments
// ---------------------------------------------------------------------------
__global__ void k_fill(const int* __restrict__ src_pg, const int* __restrict__ dst_pg,
                       const int* __restrict__ src_gp, const int* __restrict__ dst_gp,
                       const int* __restrict__ src_sp, const int* __restrict__ dst_sp,
                       const int* __restrict__ src_ps, const int* __restrict__ dst_ps)
{
    int q = blockIdx.x * blockDim.x + threadIdx.x;
    int e = q * 4;
    if (e >= ETOT) return;
    const int4 *S4, *D4;
    int nb, el;
    if (e < EBASE1)      { el = e;          S4 = (const int4*)src_pg; D4 = (const int4*)dst_pg; nb = 0; }
    else if (e < EBASE2) { el = e - EBASE1; S4 = (const int4*)src_gp; D4 = (const int4*)dst_gp; nb = NBASE1; }
    else if (e < EBASE3) { el = e - EBASE2; S4 = (const int4*)src_sp; D4 = (const int4*)dst_sp; nb = NBASE2; }
    else                 { el = e - EBASE3; S4 = (const int4*)src_ps; D4 = (const int4*)dst_ps; nb = NBASE3; }
    int4 s = __ldg(&S4[el >> 2]);
    int4 d = __ldg(&D4[el >> 2]);
    int ng, pos;
    ng = nb + d.x; pos = g_off_all[ng] + g_boff[ng >> 10] + atomicAdd(&g_cur_all[ng], 1); g_srcid[pos] = s.x;
    ng = nb + d.y; pos = g_off_all[ng] + g_boff[ng >> 10] + atomicAdd(&g_cur_all[ng], 1); g_srcid[pos] = s.y;
    ng = nb + d.z; pos = g_off_all[ng] + g_boff[ng >> 10] + atomicAdd(&g_cur_all[ng], 1); g_srcid[pos] = s.z;
    ng = nb + d.w; pos = g_off_all[ng] + g_boff[ng >> 10] + atomicAdd(&g_cur_all[ng], 1); g_srcid[pos] = s.w;
}

// ---------------------------------------------------------------------------
// 5) gather: 8 lanes per node, register accumulation, one plain store
// ---------------------------------------------------------------------------
__global__ void k_gather(const float* __restrict__ x_pfas,
                         const float* __restrict__ x_gw,
                         const float* __restrict__ x_sw)
{
    int t = blockIdx.x * blockDim.x + threadIdx.x;
    int g = t >> 3, seg = t & 7;
    if (g >= NTOT) return;

    const float4* X;
    if (g < NBASE1)      X = (const float4*)x_pfas;
    else if (g < NBASE2) X = (const float4*)x_gw;
    else if (g < NBASE3) X = (const float4*)x_sw;
    else                 X = (const float4*)x_pfas;

    int beg = g_off_all[g] + g_boff[g >> 10];
    int cn  = g_cnt_all[g];
    int i = beg, end = beg + cn;

    float4 acc = make_float4(0.f, 0.f, 0.f, 0.f);
    for (; i + 2 <= end; i += 2) {
        int s0 = __ldg(&g_srcid[i]);
        int s1 = __ldg(&g_srcid[i + 1]);
        float4 a = __ldg(&X[(size_t)s0 * 8 + seg]);
        float4 b = __ldg(&X[(size_t)s1 * 8 + seg]);
        acc.x += a.x; acc.y += a.y; acc.z += a.z; acc.w += a.w;
        acc.x += b.x; acc.y += b.y; acc.z += b.z; acc.w += b.w;
    }
    if (i < end) {
        int s0 = __ldg(&g_srcid[i]);
        float4 a = __ldg(&X[(size_t)s0 * 8 + seg]);
        acc.x += a.x; acc.y += a.y; acc.z += a.z; acc.w += a.w;
    }
    ((float4*)g_sum_all)[(size_t)g * 8 + seg] = acc;
}

// ---------------------------------------------------------------------------
// Merged epilogue (thread-per-node, f32x2 matvec with LDS.128 weight loads)
// ---------------------------------------------------------------------------
__device__ __forceinline__ void load_row(const float* base, size_t n, float inv, float x[32]) {
    const float4* r4 = (const float4*)(base + n * D);
#pragma unroll
    for (int q = 0; q < 8; q++) {
        float4 v = __ldg(&r4[q]);
        x[q * 4 + 0] = v.x * inv; x[q * 4 + 1] = v.y * inv;
        x[q * 4 + 2] = v.z * inv; x[q * 4 + 3] = v.w * inv;
    }
}

__device__ __forceinline__ void mv_acc(const float* sW, const float x[32], u64 acc[16]) {
#pragma unroll
    for (int k = 0; k < 32; k++) {
        u64 xk = pk2(x[k]);
        const float4* w4 = (const float4*)(sW + k * 32);
#pragma unroll
        for (int jq = 0; jq < 8; jq++) {
            float4 w = w4[jq];
            acc[2 * jq]     = f2fma(xk, pk2f(w.x, w.y), acc[2 * jq]);
            acc[2 * jq + 1] = f2fma(xk, pk2f(w.z, w.w), acc[2 * jq + 1]);
        }
    }
}

__device__ __forceinline__ void edge_acc(const float* __restrict__ ea, int me,
                                         const float* sWe, const float* sbe,
                                         u64 acc[16]) {
    u64 e0 = pk2(__ldg(&ea[3 * (size_t)me + 0]));
    u64 e1 = pk2(__ldg(&ea[3 * (size_t)me + 1]));
    u64 e2 = pk2(__ldg(&ea[3 * (size_t)me + 2]));
    const u64* w0 = (const u64*)(sWe);
    const u64* w1 = (const u64*)(sWe + 32);
    const u64* w2 = (const u64*)(sWe + 64);
#pragma unroll
    for (int jj = 0; jj < 16; jj++) {
        u64 a = acc[jj];
        a = f2fma(e0, w0[jj], a);
        a = f2fma(e1, w1[jj], a);
        a = f2fma(e2, w2[jj], a);
        a = f2add(a, pk2f(sbe[2 * jj], sbe[2 * jj + 1]));
        acc[jj] = a;
    }
}

struct FinArgs {
    const float *x_pfas, *x_gw, *x_sw;
    const float *ea_pg, *ea_gp;
    const float *Wl_pg, *bl_pg, *Wr_pg, *We_pg, *be_pg;
    const float *Wl_gp, *bl_gp, *Wr_gp, *We_gp, *be_gp;
    const float *Wl_ps, *bl_ps, *Wr_ps;
    const float *Wl_sp, *bl_sp, *Wr_sp;
    const float *W_out, *b_out, *a_pre;
    float *out_pfas, *out_y, *out_sw;
};

__global__ void __launch_bounds__(256) k_fin_all(FinArgs F) {
    __shared__ __align__(16) float sW[3 * 1024];
    __shared__ __align__(16) float sWe[96];
    __shared__ float sb[32], sbe[32], sWo[32];

    int b   = blockIdx.x;
    int tid = threadIdx.x;

    if (b < NB_GW) {
        // ---------------- GW phase ----------------
        for (int j = tid; j < 1024; j += 256) { sW[j] = F.Wl_pg[j]; sW[1024 + j] = F.Wr_pg[j]; }
        if (tid < 96) sWe[tid] = F.We_pg[tid];
        if (tid < 32) { sb[tid] = F.bl_pg[tid]; sbe[tid] = F.be_pg[tid]; sWo[tid] = F.W_out[tid]; }
        __syncthreads();

        int n = b * 256 + tid;
        if (n >= N_GW) return;

        u64 acc[16];
#pragma unroll
        for (int jj = 0; jj < 16; jj++) acc[jj] = pk2f(sb[2 * jj], sb[2 * jj + 1]);

        float inv = 1.0f / fmaxf((float)g_cnt_all[n], 1.0f);
        float xr[32];
        load_row(g_sum_all, (size_t)n, inv, xr);
        mv_acc(sW, xr, acc);
        load_row(F.x_gw, (size_t)n, 1.0f, xr);
        mv_acc(sW + 1024, xr, acc);

        int me = g_maxe_pg[n];
        if (me >= 0) edge_acc(F.ea_pg, me, sWe, sbe, acc);

        float yv = 0.0f;
#pragma unroll
        for (int jj = 0; jj < 16; jj++) {
            float2 h = up2(acc[jj]);
            yv += fmaxf(h.x, 0.0f) * sWo[2 * jj] + fmaxf(h.y, 0.0f) * sWo[2 * jj + 1];
        }
        yv += __ldg(&F.b_out[0]);
        float a_ = __ldg(&F.a_pre[0]);
        F.out_y[n] = (yv >= 0.0f) ? yv : a_ * yv;

    } else if (b < NB_GW + NB_PF) {
        // ---------------- PFAS phase ----------------
        for (int j = tid; j < 1024; j += 256) {
            sW[j]        = F.Wl_gp[j];
            sW[1024 + j] = F.Wl_sp[j];
            sW[2048 + j] = F.Wr_gp[j] + F.Wr_sp[j];
        }
        if (tid < 96) sWe[tid] = F.We_gp[tid];
        if (tid < 32) { sb[tid] = F.bl_gp[tid] + F.bl_sp[tid]; sbe[tid] = F.be_gp[tid]; }
        __syncthreads();

        int n = (b - NB_GW) * 256 + tid;
        if (n >= N_PFAS) return;

        u64 acc[16];
#pragma unroll
        for (int jj = 0; jj < 16; jj++) acc[jj] = pk2f(sb[2 * jj], sb[2 * jj + 1]);

        float invg = 1.0f / fmaxf((float)g_cnt_all[NBASE1 + n], 1.0f);
        float invs = 1.0f / fmaxf((float)g_cnt_all[NBASE2 + n], 1.0f);
        float xr[32];
        load_row(g_sum_all, (size_t)(NBASE1 + n), invg, xr);
        mv_acc(sW, xr, acc);
        load_row(g_sum_all, (size_t)(NBASE2 + n), invs, xr);
        mv_acc(sW + 1024, xr, acc);
        load_row(F.x_pfas, (size_t)n, 1.0f, xr);
        mv_acc(sW + 2048, xr, acc);

        int me = g_maxe_gp[n];
        if (me >= 0) edge_acc(F.ea_gp, me, sWe, sbe, acc);

        float4* o4 = (float4*)(F.out_pfas + (size_t)n * D);
#pragma unroll
        for (int q = 0; q < 8; q++) {
            float2 a = up2(acc[2 * q]);
            float2 c = up2(acc[2 * q + 1]);
            o4[q] = make_float4(fmaxf(a.x, 0.f), fmaxf(a.y, 0.f),
                                fmaxf(c.x, 0.f), fmaxf(c.y, 0.f));
        }

    } else {
        // ---------------- SW phase ----------------
        for (int j = tid; j < 1024; j += 256) { sW[j] = F.Wl_ps[j]; sW[1024 + j] = F.Wr_ps[j]; }
        if (tid < 32) sb[tid] = F.bl_ps[tid];
        __syncthreads();

        int n = (b - NB_GW - NB_PF) * 256 + tid;
        if (n >= N_SW) return;

        u64 acc[16];
#pragma unroll
        for (int jj = 0; jj < 16; jj++) acc[jj] = pk2f(sb[2 * jj], sb[2 * jj + 1]);

        float inv = 1.0f / fmaxf((float)g_cnt_all[NBASE3 + n], 1.0f);
        float xr[32];
        load_row(g_sum_all, (size_t)(NBASE3 + n), inv, xr);
        mv_acc(sW, xr, acc);
        load_row(F.x_sw, (size_t)n, 1.0f, xr);
        mv_acc(sW + 1024, xr, acc);

        float4* o4 = (float4*)(F.out_sw + (size_t)n * D);
#pragma unroll
        for (int q = 0; q < 8; q++) {
            float2 a = up2(acc[2 * q]);
            float2 c = up2(acc[2 * q + 1]);
            o4[q] = make_float4(fmaxf(a.x, 0.f), fmaxf(a.y, 0.f),
                                fmaxf(c.x, 0.f), fmaxf(c.y, 0.f));
        }
    }
}

// ---------------------------------------------------------------------------
// Launch
// ---------------------------------------------------------------------------
extern "C" void kernel_launch(void* const* d_in, const int* in_sizes, int n_in,
                              void* d_out, int out_size)
{
    const float* x_pfas = (const float*)d_in[0];
    const float* x_gw   = (const float*)d_in[1];
    const float* x_sw   = (const float*)d_in[2];
    const int*   src_pg = (const int*)d_in[3];
    const int*   dst_pg = (const int*)d_in[4];
    const float* ea_pg  = (const float*)d_in[5];
    const int*   src_gp = (const int*)d_in[6];
    const int*   dst_gp = (const int*)d_in[7];
    const float* ea_gp  = (const float*)d_in[8];
    const int*   src_ps = (const int*)d_in[9];
    const int*   dst_ps = (const int*)d_in[10];
    const int*   src_sp = (const int*)d_in[11];
    const int*   dst_sp = (const int*)d_in[12];

    float* out = (float*)d_out;

    // 1) init
    k_init<<<512, 256>>>();

    // 2) count (+maxe)
    int cb = (ETOT / 4 + 255) / 256;
    k_count<<<cb, 256>>>(dst_pg, dst_gp, dst_sp, dst_ps);

    // 3) scan
    k_scan1<<<NB_SCAN, 256>>>();
    k_scan2<<<1, 512>>>();

    // 4) fill CSR
    k_fill<<<cb, 256>>>(src_pg, dst_pg, src_gp, dst_gp,
                        src_sp, dst_sp, src_ps, dst_ps);

    // 5) gather (8 lanes per node)
    k_gather<<<(NTOT * 8 + 255) / 256, 256>>>(x_pfas, x_gw, x_sw);

    // 6) merged epilogue
    {
        FinArgs F;
        F.x_pfas = x_pfas; F.x_gw = x_gw; F.x_sw = x_sw;
        F.ea_pg = ea_pg;   F.ea_gp = ea_gp;
        F.Wl_pg = (const float*)d_in[13]; F.bl_pg = (const float*)d_in[14];
        F.Wr_pg = (const float*)d_in[15]; F.We_pg = (const float*)d_in[16];
        F.be_pg = (const float*)d_in[17];
        F.Wl_gp = (const float*)d_in[18]; F.bl_gp = (const float*)d_in[19];
        F.Wr_gp = (const float*)d_in[20]; F.We_gp = (const float*)d_in[21];
        F.be_gp = (const float*)d_in[22];
        F.Wl_ps = (const float*)d_in[23]; F.bl_ps = (const float*)d_in[24];
        F.Wr_ps = (const float*)d_in[25];
        F.Wl_sp = (const float*)d_in[26]; F.bl_sp = (const float*)d_in[27];
        F.Wr_sp = (const float*)d_in[28];
        F.W_out = (const float*)d_in[29]; F.b_out = (const float*)d_in[30];
        F.a_pre = (const float*)d_in[31];
        F.out_pfas = out;
        F.out_y    = out + OFF_Y;
        F.out_sw   = out + OFF_SW;

        k_fin_all<<<NB_GW + NB_PF + NB_SW, 256>>>(F);
    }

    (void)in_sizes; (void)n_in; (void)out_size;
}

// round 6
// speedup vs baseline: 1.1608x; 1.1608x over previous
#include <cuda_runtime.h>

// ---------------------------------------------------------------------------
// Problem constants
// ---------------------------------------------------------------------------
#define N_PFAS 50000
#define N_GW   200000
#define N_SW   20000
#define D      32
#define E_PG   2000000
#define E_GP   2000000
#define E_PS   1000000
#define E_SP   1000000

#define OFF_Y   (N_PFAS * D)
#define OFF_SW  (N_PFAS * D + N_GW)

#define NB_GW  ((N_GW + 255) / 256)     // 782
#define NB_PF  ((N_PFAS + 255) / 256)   // 196
#define NB_SW  ((N_SW + 255) / 256)     // 79

typedef unsigned long long u64;

// ---------------------------------------------------------------------------
// Scratch (device globals; allocation-free). 16B aligned for v4 atomics/loads.
// ---------------------------------------------------------------------------
__device__ __align__(16) float g_sum_pg[(size_t)N_GW * D];
__device__ float g_cnt_pg[N_GW];
__device__ int   g_maxe_pg[N_GW];

__device__ __align__(16) float g_sum_gp[(size_t)N_PFAS * D];
__device__ float g_cnt_gp[N_PFAS];
__device__ int   g_maxe_gp[N_PFAS];

__device__ __align__(16) float g_sum_sp[(size_t)N_PFAS * D];
__device__ float g_cnt_sp[N_PFAS];

__device__ __align__(16) float g_sum_ps[(size_t)N_SW * D];
__device__ float g_cnt_ps[N_SW];

// ---------------------------------------------------------------------------
// Packed f32x2 helpers (sm_100+)
// ---------------------------------------------------------------------------
__device__ __forceinline__ u64 pk2(float x) {
    u64 d; unsigned xi = __float_as_uint(x);
    asm("mov.b64 %0, {%1, %1};" : "=l"(d) : "r"(xi));
    return d;
}
__device__ __forceinline__ u64 pk2f(float a, float b) {
    u64 d; unsigned ai = __float_as_uint(a), bi = __float_as_uint(b);
    asm("mov.b64 %0, {%1, %2};" : "=l"(d) : "r"(ai), "r"(bi));
    return d;
}
__device__ __forceinline__ u64 f2fma(u64 a, u64 b, u64 c) {
    u64 d; asm("fma.rn.f32x2 %0, %1, %2, %3;" : "=l"(d) : "l"(a), "l"(b), "l"(c));
    return d;
}
__device__ __forceinline__ u64 f2add(u64 a, u64 b) {
    u64 d; asm("add.rn.f32x2 %0, %1, %2;" : "=l"(d) : "l"(a), "l"(b));
    return d;
}
__device__ __forceinline__ float2 up2(u64 a) {
    unsigned lo, hi;
    asm("mov.b64 {%0, %1}, %2;" : "=r"(lo), "=r"(hi) : "l"(a));
    return make_float2(__uint_as_float(lo), __uint_as_float(hi));
}

// ---------------------------------------------------------------------------
// Vector atomic: red.global.add.v4.f32 (sm_90+)
// ---------------------------------------------------------------------------
__device__ __forceinline__ void red_add_v4(float* addr, float4 v) {
    asm volatile("red.global.add.v4.f32 [%0], {%1,%2,%3,%4};"
                 :: "l"(addr), "f"(v.x), "f"(v.y), "f"(v.z), "f"(v.w)
                 : "memory");
}

// ---------------------------------------------------------------------------
// Init
// ---------------------------------------------------------------------------
__global__ void k_init() {
    int i = blockIdx.x * blockDim.x + threadIdx.x;
    int stride = gridDim.x * blockDim.x;
    for (int j = i; j < N_GW * D;   j += stride) g_sum_pg[j] = 0.f;
    for (int j = i; j < N_PFAS * D; j += stride) g_sum_gp[j] = 0.f;
    for (int j = i; j < N_PFAS * D; j += stride) g_sum_sp[j] = 0.f;
    for (int j = i; j < N_SW * D;   j += stride) g_sum_ps[j] = 0.f;
    for (int j = i; j < N_GW;   j += stride) { g_cnt_pg[j] = 0.f; g_maxe_pg[j] = -1; }
    for (int j = i; j < N_PFAS; j += stride) { g_cnt_gp[j] = 0.f; g_maxe_gp[j] = -1;
                                               g_cnt_sp[j] = 0.f; }
    for (int j = i; j < N_SW;   j += stride) g_cnt_ps[j] = 0.f;
}

// ---------------------------------------------------------------------------
// Fused edge aggregation: all 4 relations in one launch.
// 8 lanes per edge-group; each group processes 4 consecutive edges (ILP=4).
// ---------------------------------------------------------------------------
struct AggArgs {
    const float4* x[4];
    const int4*   src[4];
    const int4*   dst[4];
    float*        sum[4];
    float*        cnt[4];
    int*          maxe[4];
    int           ngroups[4];
    int           blkEnd[4];
};

__global__ void k_agg_all(AggArgs A) {
    int b = blockIdx.x;
    int r, base;
    if (b < A.blkEnd[0])      { r = 0; base = 0; }
    else if (b < A.blkEnd[1]) { r = 1; base = A.blkEnd[0]; }
    else if (b < A.blkEnd[2]) { r = 2; base = A.blkEnd[1]; }
    else                      { r = 3; base = A.blkEnd[2]; }

    int t   = (b - base) * blockDim.x + threadIdx.x;
    int g   = t >> 3;
    int seg = t & 7;
    if (g >= A.ngroups[r]) return;

    int4 s4 = __ldg(&A.src[r][g]);
    int4 d4 = __ldg(&A.dst[r][g]);
    const float4* X = A.x[r];
    float* S = A.sum[r];

    float4 v0 = __ldg(&X[(size_t)s4.x * 8 + seg]);
    float4 v1 = __ldg(&X[(size_t)s4.y * 8 + seg]);
    float4 v2 = __ldg(&X[(size_t)s4.z * 8 + seg]);
    float4 v3 = __ldg(&X[(size_t)s4.w * 8 + seg]);

    red_add_v4(&S[(size_t)d4.x * D + seg * 4], v0);
    red_add_v4(&S[(size_t)d4.y * D + seg * 4], v1);
    red_add_v4(&S[(size_t)d4.z * D + seg * 4], v2);
    red_add_v4(&S[(size_t)d4.w * D + seg * 4], v3);

    if (seg == 0) {
        float* C = A.cnt[r];
        atomicAdd(&C[d4.x], 1.0f);
        atomicAdd(&C[d4.y], 1.0f);
        atomicAdd(&C[d4.z], 1.0f);
        atomicAdd(&C[d4.w], 1.0f);
        int* M = A.maxe[r];
        if (M) {
            int e0 = g * 4;
            atomicMax(&M[d4.x], e0);
            atomicMax(&M[d4.y], e0 + 1);
            atomicMax(&M[d4.z], e0 + 2);
            atomicMax(&M[d4.w], e0 + 3);
        }
    }
}

// ---------------------------------------------------------------------------
// Merged thread-per-node epilogue. Streaming matvec: x-row consumed float4 at
// a time (no xr[32] buffer) -> ~50 regs -> 4 blocks/SM.
// ---------------------------------------------------------------------------
__device__ __forceinline__ void mv_stream(const float* sW, const float* xb,
                                          size_t n, float inv, u64 acc[16]) {
    const float4* r4 = (const float4*)(xb + n * D);
#pragma unroll
    for (int q = 0; q < 8; q++) {
        float4 v = __ldg(&r4[q]);
        float xv[4] = { v.x * inv, v.y * inv, v.z * inv, v.w * inv };
#pragma unroll
        for (int c = 0; c < 4; c++) {
            u64 xk = pk2(xv[c]);
            const ulonglong2* w2 = (const ulonglong2*)(sW + (q * 4 + c) * 32);
#pragma unroll
            for (int jq = 0; jq < 4; jq++) {
                ulonglong2 w = w2[jq];
                acc[4 * jq]     = f2fma(xk, w.x, acc[4 * jq]);
                acc[4 * jq + 1] = f2fma(xk, w.y, acc[4 * jq + 1]);
            }
#pragma unroll
            for (int jq = 0; jq < 4; jq++) {
                ulonglong2 w = w2[jq + 4];
                // note: second half covers acc[2], acc[3] slots of each group
                acc[4 * jq + 2] = f2fma(xk, w.x, acc[4 * jq + 2]);
                acc[4 * jq + 3] = f2fma(xk, w.y, acc[4 * jq + 3]);
            }
        }
    }
}

__device__ __forceinline__ void edge_acc(const float* __restrict__ ea, int me,
                                         const float* sWe, const float* sbe,
                                         u64 acc[16]) {
    u64 e0 = pk2(__ldg(&ea[3 * (size_t)me + 0]));
    u64 e1 = pk2(__ldg(&ea[3 * (size_t)me + 1]));
    u64 e2 = pk2(__ldg(&ea[3 * (size_t)me + 2]));
    const u64* w0 = (const u64*)(sWe);
    const u64* w1 = (const u64*)(sWe + 32);
    const u64* w2 = (const u64*)(sWe + 64);
#pragma unroll
    for (int jj = 0; jj < 16; jj++) {
        u64 a = acc[jj];
        a = f2fma(e0, w0[jj], a);
        a = f2fma(e1, w1[jj], a);
        a = f2fma(e2, w2[jj], a);
        a = f2add(a, pk2f(sbe[2 * jj], sbe[2 * jj + 1]));
        acc[jj] = a;
    }
}

struct FinArgs {
    const float *x_pfas, *x_gw, *x_sw;
    const float *ea_pg, *ea_gp;
    const float *Wl_pg, *bl_pg, *Wr_pg, *We_pg, *be_pg;
    const float *Wl_gp, *bl_gp, *Wr_gp, *We_gp, *be_gp;
    const float *Wl_ps, *bl_ps, *Wr_ps;
    const float *Wl_sp, *bl_sp, *Wr_sp;
    const float *W_out, *b_out, *a_pre;
    float *out_pfas, *out_y, *out_sw;
};

// NOTE on acc layout: with mv_stream's indexing, acc[4*jq + m] corresponds to
// output pair index jj = (m<2 ? jq*2+... ). Concretely: acc[4q], acc[4q+1]
// hold output floats {16q+0..3}? To keep this simple and correct, we define
// the mapping ONCE: weight pair p (p=0..15, covering outputs 2p,2p+1) is
// accumulated into acc[IDX(p)] where IDX(p) = (p<8) ? (p/2)*4 + (p&1)
//                                            : ((p-8)/2)*4 + 2 + (p&1).
// The bias init, edge_acc, and the output unpack below all use IDX().
__device__ __forceinline__ int IDX(int p) {
    return (p < 8) ? (p >> 1) * 4 + (p & 1)
                   : ((p - 8) >> 1) * 4 + 2 + (p & 1);
}

__global__ void __launch_bounds__(256, 4) k_fin_all(FinArgs F) {
    __shared__ __align__(16) float sW[3 * 1024];
    __shared__ __align__(16) float sWe[96];
    __shared__ float sb[32], sbe[32], sWo[32];

    int b   = blockIdx.x;
    int tid = threadIdx.x;

    if (b < NB_GW) {
        // ---------------- GW phase ----------------
        for (int j = tid; j < 1024; j += 256) { sW[j] = F.Wl_pg[j]; sW[1024 + j] = F.Wr_pg[j]; }
        if (tid < 96) sWe[tid] = F.We_pg[tid];
        if (tid < 32) { sb[tid] = F.bl_pg[tid]; sbe[tid] = F.be_pg[tid]; sWo[tid] = F.W_out[tid]; }
        __syncthreads();

        int n = b * 256 + tid;
        if (n >= N_GW) return;

        u64 acc[16];
#pragma unroll
        for (int p = 0; p < 16; p++) acc[IDX(p)] = pk2f(sb[2 * p], sb[2 * p + 1]);

        float inv = 1.0f / fmaxf(g_cnt_pg[n], 1.0f);
        mv_stream(sW, g_sum_pg, (size_t)n, inv, acc);
        mv_stream(sW + 1024, F.x_gw, (size_t)n, 1.0f, acc);

        int me = g_maxe_pg[n];
        if (me >= 0) {
            // edge_acc uses pair order p -> acc[IDX(p)]
            u64 e0 = pk2(__ldg(&F.ea_pg[3 * (size_t)me + 0]));
            u64 e1 = pk2(__ldg(&F.ea_pg[3 * (size_t)me + 1]));
            u64 e2 = pk2(__ldg(&F.ea_pg[3 * (size_t)me + 2]));
            const u64* w0 = (const u64*)(sWe);
            const u64* w1 = (const u64*)(sWe + 32);
            const u64* w2 = (const u64*)(sWe + 64);
#pragma unroll
            for (int p = 0; p < 16; p++) {
                u64 a = acc[IDX(p)];
                a = f2fma(e0, w0[p], a);
                a = f2fma(e1, w1[p], a);
                a = f2fma(e2, w2[p], a);
                a = f2add(a, pk2f(sbe[2 * p], sbe[2 * p + 1]));
                acc[IDX(p)] = a;
            }
        }

        float yv = 0.0f;
#pragma unroll
        for (int p = 0; p < 16; p++) {
            float2 h = up2(acc[IDX(p)]);
            yv += fmaxf(h.x, 0.0f) * sWo[2 * p] + fmaxf(h.y, 0.0f) * sWo[2 * p + 1];
        }
        yv += __ldg(&F.b_out[0]);
        float a_ = __ldg(&F.a_pre[0]);
        F.out_y[n] = (yv >= 0.0f) ? yv : a_ * yv;

    } else if (b < NB_GW + NB_PF) {
        // ---------------- PFAS phase ----------------
        for (int j = tid; j < 1024; j += 256) {
            sW[j]        = F.Wl_gp[j];
            sW[1024 + j] = F.Wl_sp[j];
            sW[2048 + j] = F.Wr_gp[j] + F.Wr_sp[j];
        }
        if (tid < 96) sWe[tid] = F.We_gp[tid];
        if (tid < 32) { sb[tid] = F.bl_gp[tid] + F.bl_sp[tid]; sbe[tid] = F.be_gp[tid]; }
        __syncthreads();

        int n = (b - NB_GW) * 256 + tid;
        if (n >= N_PFAS) return;

        u64 acc[16];
#pragma unroll
        for (int p = 0; p < 16; p++) acc[IDX(p)] = pk2f(sb[2 * p], sb[2 * p + 1]);

        float invg = 1.0f / fmaxf(g_cnt_gp[n], 1.0f);
        float invs = 1.0f / fmaxf(g_cnt_sp[n], 1.0f);
        mv_stream(sW, g_sum_gp, (size_t)n, invg, acc);
        mv_stream(sW + 1024, g_sum_sp, (size_t)n, invs, acc);
        mv_stream(sW + 2048, F.x_pfas, (size_t)n, 1.0f, acc);

        int me = g_maxe_gp[n];
        if (me >= 0) {
            u64 e0 = pk2(__ldg(&F.ea_gp[3 * (size_t)me + 0]));
            u64 e1 = pk2(__ldg(&F.ea_gp[3 * (size_t)me + 1]));
            u64 e2 = pk2(__ldg(&F.ea_gp[3 * (size_t)me + 2]));
            const u64* w0 = (const u64*)(sWe);
            const u64* w1 = (const u64*)(sWe + 32);
            const u64* w2 = (const u64*)(sWe + 64);
#pragma unroll
            for (int p = 0; p < 16; p++) {
                u64 a = acc[IDX(p)];
                a = f2fma(e0, w0[p], a);
                a = f2fma(e1, w1[p], a);
                a = f2fma(e2, w2[p], a);
                a = f2add(a, pk2f(sbe[2 * p], sbe[2 * p + 1]));
                acc[IDX(p)] = a;
            }
        }

        float4* o4 = (float4*)(F.out_pfas + (size_t)n * D);
#pragma unroll
        for (int p = 0; p < 16; p += 2) {
            float2 a = up2(acc[IDX(p)]);
            float2 c = up2(acc[IDX(p + 1)]);
            o4[p >> 1] = make_float4(fmaxf(a.x, 0.f), fmaxf(a.y, 0.f),
                                     fmaxf(c.x, 0.f), fmaxf(c.y, 0.f));
        }

    } else {
        // ---------------- SW phase ----------------
        for (int j = tid; j < 1024; j += 256) { sW[j] = F.Wl_ps[j]; sW[1024 + j] = F.Wr_ps[j]; }
        if (tid < 32) sb[tid] = F.bl_ps[tid];
        __syncthreads();

        int n = (b - NB_GW - NB_PF) * 256 + tid;
        if (n >= N_SW) return;

        u64 acc[16];
#pragma unroll
        for (int p = 0; p < 16; p++) acc[IDX(p)] = pk2f(sb[2 * p], sb[2 * p + 1]);

        float inv = 1.0f / fmaxf(g_cnt_ps[n], 1.0f);
        mv_stream(sW, g_sum_ps, (size_t)n, inv, acc);
        mv_stream(sW + 1024, F.x_sw, (size_t)n, 1.0f, acc);

        float4* o4 = (float4*)(F.out_sw + (size_t)n * D);
#pragma unroll
        for (int p = 0; p < 16; p += 2) {
            float2 a = up2(acc[IDX(p)]);
            float2 c = up2(acc[IDX(p + 1)]);
            o4[p >> 1] = make_float4(fmaxf(a.x, 0.f), fmaxf(a.y, 0.f),
                                     fmaxf(c.x, 0.f), fmaxf(c.y, 0.f));
        }
    }
}

// ---------------------------------------------------------------------------
// Launch
// ---------------------------------------------------------------------------
extern "C" void kernel_launch(void* const* d_in, const int* in_sizes, int n_in,
                              void* d_out, int out_size)
{
    const float* x_pfas = (const float*)d_in[0];
    const float* x_gw   = (const float*)d_in[1];
    const float* x_sw   = (const float*)d_in[2];
    const int*   src_pg = (const int*)d_in[3];
    const int*   dst_pg = (const int*)d_in[4];
    const float* ea_pg  = (const float*)d_in[5];
    const int*   src_gp = (const int*)d_in[6];
    const int*   dst_gp = (const int*)d_in[7];
    const float* ea_gp  = (const float*)d_in[8];
    const int*   src_ps = (const int*)d_in[9];
    const int*   dst_ps = (const int*)d_in[10];
    const int*   src_sp = (const int*)d_in[11];
    const int*   dst_sp = (const int*)d_in[12];

    float* out = (float*)d_out;

    float *p_sum_pg, *p_cnt_pg, *p_sum_gp, *p_cnt_gp, *p_sum_sp, *p_cnt_sp, *p_sum_ps, *p_cnt_ps;
    int *p_maxe_pg, *p_maxe_gp;
    cudaGetSymbolAddress((void**)&p_sum_pg, g_sum_pg);
    cudaGetSymbolAddress((void**)&p_cnt_pg, g_cnt_pg);
    cudaGetSymbolAddress((void**)&p_sum_gp, g_sum_gp);
    cudaGetSymbolAddress((void**)&p_cnt_gp, g_cnt_gp);
    cudaGetSymbolAddress((void**)&p_sum_sp, g_sum_sp);
    cudaGetSymbolAddress((void**)&p_cnt_sp, g_cnt_sp);
    cudaGetSymbolAddress((void**)&p_sum_ps, g_sum_ps);
    cudaGetSymbolAddress((void**)&p_cnt_ps, g_cnt_ps);
    cudaGetSymbolAddress((void**)&p_maxe_pg, g_maxe_pg);
    cudaGetSymbolAddress((void**)&p_maxe_gp, g_maxe_gp);

    // 1) init scratch
    k_init<<<2048, 256>>>();

    // 2) fused edge aggregation
    {
        AggArgs A;
        const float* xs[4]  = { x_pfas, x_gw, x_sw, x_pfas };
        const int*   ss[4]  = { src_pg, src_gp, src_sp, src_ps };
        const int*   ds[4]  = { dst_pg, dst_gp, dst_sp, dst_ps };
        float*       sm[4]  = { p_sum_pg, p_sum_gp, p_sum_sp, p_sum_ps };
        float*       cn[4]  = { p_cnt_pg, p_cnt_gp, p_cnt_sp, p_cnt_ps };
        int*         mx[4]  = { p_maxe_pg, p_maxe_gp, nullptr, nullptr };
        int          Es[4]  = { E_PG, E_GP, E_SP, E_PS };
        int blocks = 0;
        for (int r = 0; r < 4; r++) {
            A.x[r]   = (const float4*)xs[r];
            A.src[r] = (const int4*)ss[r];
            A.dst[r] = (const int4*)ds[r];
            A.sum[r] = sm[r];
            A.cnt[r] = cn[r];
            A.maxe[r] = mx[r];
            int ng = Es[r] / 4;
            A.ngroups[r] = ng;
            blocks += (ng * 8 + 255) / 256;
            A.blkEnd[r] = blocks;
        }
        k_agg_all<<<blocks, 256>>>(A);
    }

    // 3) merged epilogue (one launch, streaming matvec)
    {
        FinArgs F;
        F.x_pfas = x_pfas; F.x_gw = x_gw; F.x_sw = x_sw;
        F.ea_pg = ea_pg;   F.ea_gp = ea_gp;
        F.Wl_pg = (const float*)d_in[13]; F.bl_pg = (const float*)d_in[14];
        F.Wr_pg = (const float*)d_in[15]; F.We_pg = (const float*)d_in[16];
        F.be_pg = (const float*)d_in[17];
        F.Wl_gp = (const float*)d_in[18]; F.bl_gp = (const float*)d_in[19];
        F.Wr_gp = (const float*)d_in[20]; F.We_gp = (const float*)d_in[21];
        F.be_gp = (const float*)d_in[22];
        F.Wl_ps = (const float*)d_in[23]; F.bl_ps = (const float*)d_in[24];
        F.Wr_ps = (const float*)d_in[25];
        F.Wl_sp = (const float*)d_in[26]; F.bl_sp = (const float*)d_in[27];
        F.Wr_sp = (const float*)d_in[28];
        F.W_out = (const float*)d_in[29]; F.b_out = (const float*)d_in[30];
        F.a_pre = (const float*)d_in[31];
        F.out_pfas = out;
        F.out_y    = out + OFF_Y;
        F.out_sw   = out + OFF_SW;

        k_fin_all<<<NB_GW + NB_PF + NB_SW, 256>>>(F);
    }

    (void)in_sizes; (void)n_in; (void)out_size;
}